// round 15
// baseline (speedup 1.0000x reference)
#include <cuda_runtime.h>
#include <cstdint>

#define DEV_INLINE __device__ __forceinline__

// ---------------- problem constants ----------------
// B=2, TV=8192, TL=256, E=2048, H=8, D=256, VD=256, LD=768, scale=0.0625

// ---------------- scratch ----------------
__device__ __align__(16) float g_q   [(size_t)16 * 8192 * 256];   // [z][t][d] tf32
__device__ __align__(16) float g_vv  [(size_t)16 * 8192 * 256];   // [z][t][d] tf32
__device__ __align__(16) float g_k   [16 * 256 * 256];            // [z][s][d] tf32
__device__ __align__(16) float g_vl  [16 * 256 * 256];            // [z][s][d] tf32, pre-masked
__device__ __align__(16) float g_W   [(size_t)16 * 8192 * 256];   // [z][t][s] exp tf32
__device__ __align__(16) float g_outv1[(size_t)2 * 8192 * 2048];  // [b][t][E] tf32
__device__ __align__(16) float g_outl1[2 * 256 * 2048];           // [b][s][E] (split-K acc)
__device__ float g_rowZ[16 * 8192];
__device__ float g_colZ[16 * 256];
__device__ float g_maskf[512];

// ---------------- helpers ----------------
DEV_INLINE float tf32r(float x) {
    uint32_t u;
    asm("cvt.rna.tf32.f32 %0, %1;" : "=r"(u) : "f"(x));
    return __uint_as_float(u);
}
DEV_INLINE uint32_t fu(float x) { return __float_as_uint(x); }
DEV_INLINE void cvt4(float4& v) {
    v.x = tf32r(v.x); v.y = tf32r(v.y); v.z = tf32r(v.z); v.w = tf32r(v.w);
}

DEV_INLINE void mma8(float (&c)[4], uint32_t a0, uint32_t a1, uint32_t a2, uint32_t a3,
                     uint32_t b0, uint32_t b1) {
    asm volatile(
        "mma.sync.aligned.m16n8k8.row.col.f32.tf32.tf32.f32 "
        "{%0,%1,%2,%3}, {%4,%5,%6,%7}, {%8,%9}, {%0,%1,%2,%3};\n"
        : "+f"(c[0]), "+f"(c[1]), "+f"(c[2]), "+f"(c[3])
        : "r"(a0), "r"(a1), "r"(a2), "r"(a3), "r"(b0), "r"(b1));
}

DEV_INLINE void cp16(float* dst, const float* src) {
    uint32_t d = (uint32_t)__cvta_generic_to_shared(dst);
    asm volatile("cp.async.cg.shared.global [%0], [%1], 16;\n" :: "r"(d), "l"(src));
}
DEV_INLINE void cpcommit() { asm volatile("cp.async.commit_group;\n"); }
DEV_INLINE void cpwait1()  { asm volatile("cp.async.wait_group 1;\n"); }

// ================= GEMM core: linear A staging + permuted-k float4 frags =================
// A row-major [M][K] staged at stride 48 -> fragment = one float4 (LDS.128).
// Logical k permutation per 16-col group g: step s uses physical k = g*16 + 4*tig + 2*s (+1).
// B NT [N][K]: same stride-48 float4 layout as A.
// B KN [K][N]: stride NB with XOR swizzle at float4 granularity:
//   element (k, col) at  k*NB + 4*((col>>2) ^ (2*((k>>2)&3))) + (col&3)
constexpr int BM = 128;
constexpr int AST = 48;
__host__ __device__ constexpr int smem_new(int NB, bool BNT) {
    int a = 128 * AST;
    int b = BNT ? NB * AST : 32 * NB;
    return 2 * (a + b) * 4;
}

template<int NB, bool BNT>
DEV_INLINE void load_stage(const float* A, const float* B, int k0,
                           int lda, int ldb, int m0, int n0,
                           float* As, float* Bs, int tid) {
    #pragma unroll
    for (int i = 0; i < 4; i++) {
        int lin = tid + i * 256;
        int r = lin >> 3, c4 = (lin & 7) << 2;
        cp16(As + r * AST + c4, A + (size_t)(m0 + r) * lda + k0 + c4);
    }
    if (BNT) {
        #pragma unroll
        for (int i = 0; i < NB / 32; i++) {
            int lin = tid + i * 256;
            int r = lin >> 3, c4 = (lin & 7) << 2;
            cp16(Bs + r * AST + c4, B + (size_t)(n0 + r) * ldb + k0 + c4);
        }
    } else {
        #pragma unroll
        for (int i = 0; i < NB / 32; i++) {
            int lin = tid + i * 256;
            int kk = lin / (NB / 4);
            int g  = lin % (NB / 4);
            int swz = g ^ (2 * ((kk >> 2) & 3));
            cp16(Bs + kk * NB + swz * 4, B + (size_t)(k0 + kk) * ldb + n0 + (g << 2));
        }
    }
}

template<int NB, bool BNT, bool CVTA, bool CVTB>
DEV_INLINE void compute_stage(const float* As, const float* Bs,
                              int wm, int wn, int gid, int tig,
                              float (&acc)[NB == 128 ? 4 : 2][4][4]) {
    constexpr int MI = (NB == 128 ? 4 : 2);
    const float4* As4 = (const float4*)As;   // row stride = 12 float4
    const float4* Bs4 = (const float4*)Bs;
    #pragma unroll
    for (int g = 0; g < 2; g++) {
        float4 Fa[MI], Fb[MI];
        #pragma unroll
        for (int im = 0; im < MI; im++) {
            int row = wm + im * 16 + gid;
            Fa[im] = As4[row * 12 + g * 4 + tig];
            Fb[im] = As4[(row + 8) * 12 + g * 4 + tig];
            if (CVTA) { cvt4(Fa[im]); cvt4(Fb[im]); }
        }
        if (BNT) {
            float4 Bf[4];
            #pragma unroll
            for (int jn = 0; jn < 4; jn++) {
                Bf[jn] = Bs4[(wn + jn * 8 + gid) * 12 + g * 4 + tig];
                if (CVTB) cvt4(Bf[jn]);
            }
            #pragma unroll
            for (int im = 0; im < MI; im++)
                #pragma unroll
                for (int jn = 0; jn < 4; jn++)
                    mma8(acc[im][jn], fu(Fa[im].x), fu(Fb[im].x), fu(Fa[im].y), fu(Fb[im].y),
                         fu(Bf[jn].x), fu(Bf[jn].y));
            #pragma unroll
            for (int im = 0; im < MI; im++)
                #pragma unroll
                for (int jn = 0; jn < 4; jn++)
                    mma8(acc[im][jn], fu(Fa[im].z), fu(Fb[im].z), fu(Fa[im].w), fu(Fb[im].w),
                         fu(Bf[jn].z), fu(Bf[jn].w));
        } else {
            #pragma unroll
            for (int s = 0; s < 2; s++) {
                const int klo = g * 16 + 4 * tig + 2 * s;
                uint32_t blo[4], bhi[4];
                #pragma unroll
                for (int jn = 0; jn < 4; jn++) {
                    int col = wn + jn * 8 + gid;
                    int scol = (((col >> 2) ^ (2 * tig)) << 2) + (col & 3);
                    float lo = Bs[klo * NB + scol];
                    float hi = Bs[(klo + 1) * NB + scol];
                    if (CVTB) { lo = tf32r(lo); hi = tf32r(hi); }
                    blo[jn] = fu(lo); bhi[jn] = fu(hi);
                }
                const int c0 = 2 * s, c1 = 2 * s + 1;
                #pragma unroll
                for (int im = 0; im < MI; im++) {
                    const float* fa = (const float*)&Fa[im];
                    const float* fb = (const float*)&Fb[im];
                    #pragma unroll
                    for (int jn = 0; jn < 4; jn++)
                        mma8(acc[im][jn], fu(fa[c0]), fu(fb[c0]), fu(fa[c1]), fu(fb[c1]),
                             blo[jn], bhi[jn]);
                }
            }
        }
    }
}

template<int NB, bool BNT, bool CVTA, bool CVTB>
DEV_INLINE void gemm_core(const float* A, const float* B, int kbeg, int kcnt,
                          int lda, int ldb, int m0, int n0,
                          float (&acc)[NB == 128 ? 4 : 2][4][4]) {
    extern __shared__ float smem[];
    constexpr int MI = (NB == 128 ? 4 : 2);
    constexpr int BSZ = BNT ? NB * AST : 32 * NB;
    constexpr int SF = 128 * AST + BSZ;

    const int tid = threadIdx.x;
    const int lane = tid & 31, warp = tid >> 5;
    const int wm = (NB == 128) ? (warp >> 2) * 64 : (warp & 3) * 32;
    const int wn = (NB == 128) ? (warp & 3) * 32 : (warp >> 2) * 32;
    const int gid = lane >> 2, tig = lane & 3;

    #pragma unroll
    for (int i = 0; i < MI; i++)
        #pragma unroll
        for (int j = 0; j < 4; j++)
            #pragma unroll
            for (int q = 0; q < 4; q++) acc[i][j][q] = 0.f;

    const int nk = kcnt >> 5;
    load_stage<NB, BNT>(A, B, kbeg, lda, ldb, m0, n0, smem, smem + 128 * AST, tid);
    cpcommit();
    for (int i = 0; i < nk; i++) {
        if (i + 1 < nk) {
            float* D = smem + ((i + 1) & 1) * SF;
            load_stage<NB, BNT>(A, B, kbeg + ((i + 1) << 5), lda, ldb, m0, n0,
                                D, D + 128 * AST, tid);
        }
        cpcommit();
        cpwait1();
        __syncthreads();
        const float* S = smem + (i & 1) * SF;
        compute_stage<NB, BNT, CVTA, CVTB>(S, S + 128 * AST, wm, wn, gid, tig, acc);
        __syncthreads();
    }
}

// ================= ATRANS core (step 6 only): A [m][k] stored at A[k*lda+m] =================
constexpr int SM_AT = 2 * (32 * 136 + 32 * 136) * 4;   // 69632

DEV_INLINE void load_stage_at(const float* A, const float* B, int k0,
                              int lda, int ldb, int m0, int n0,
                              float* As, float* Bs, int tid) {
    #pragma unroll
    for (int i = 0; i < 4; i++) {
        int lin = tid + i * 256;
        int kk = lin >> 5, m4 = (lin & 31) << 2;
        cp16(As + kk * 136 + m4, A + (size_t)(k0 + kk) * lda + m0 + m4);
    }
    #pragma unroll
    for (int i = 0; i < 4; i++) {
        int lin = tid + i * 256;
        int kk = lin >> 5, n4 = (lin & 31) << 2;
        cp16(Bs + kk * 136 + n4, B + (size_t)(k0 + kk) * ldb + n0 + n4);
    }
}

DEV_INLINE void compute_stage_at(const float* As, const float* Bs,
                                 int wm, int wn, int gid, int tig,
                                 float (&acc)[4][4][4]) {
    #pragma unroll
    for (int ks = 0; ks < 4; ks++) {
        const int kb = ks << 3;
        uint32_t a[4][4], b[4][2];
        #pragma unroll
        for (int im = 0; im < 4; im++) {
            int row = wm + im * 16 + gid;
            a[im][0] = fu(As[(kb + tig) * 136 + row]);
            a[im][1] = fu(As[(kb + tig) * 136 + row + 8]);
            a[im][2] = fu(As[(kb + tig + 4) * 136 + row]);
            a[im][3] = fu(As[(kb + tig + 4) * 136 + row + 8]);
        }
        #pragma unroll
        for (int jn = 0; jn < 4; jn++) {
            int col = wn + jn * 8 + gid;
            b[jn][0] = fu(Bs[(kb + tig) * 136 + col]);
            b[jn][1] = fu(Bs[(kb + tig + 4) * 136 + col]);
        }
        #pragma unroll
        for (int im = 0; im < 4; im++)
            #pragma unroll
            for (int jn = 0; jn < 4; jn++)
                mma8(acc[im][jn], a[im][0], a[im][1], a[im][2], a[im][3], b[jn][0], b[jn][1]);
    }
}

// ---------------- epilogues ----------------
struct EpiOutV {
    const float* rowZ; float* out;
    DEV_INLINE void operator()(int z, int r, int c, float v) const {
        int b = z >> 3, h = z & 7;
        out[((size_t)b * 8192 + r) * 2048 + h * 256 + c] = tf32r(v / rowZ[z * 8192 + r]);
    }
};
struct EpiBias {
    const float* bias; float* out; int ldc;
    DEV_INLINE void operator()(int, int r, int c, float v) const {
        out[(size_t)r * ldc + c] = v + bias[c];
    }
};
struct EpiAtomL {
    float* out;
    DEV_INLINE void operator()(int z, int r, int c, float v) const {
        int b = z >> 3, h = z & 7;
        atomicAdd(&out[((size_t)b * 256 + r) * 2048 + h * 256 + c], v);
    }
};
struct EpiAtomPlain {
    float* out; int ldc;
    DEV_INLINE void operator()(int, int r, int c, float v) const {
        atomicAdd(&out[(size_t)r * ldc + c], v);
    }
};

// ---------------- generic GEMM kernel ----------------
struct GemmP {
    const float* A; const float* B;
    int K, lda, ldb;
    long aB, bB;
    int ksplit;
};

template<int NB, bool BNT, bool CVTA, bool CVTB, class Epi>
__global__ __launch_bounds__(256, 2) void gemm_kernel(GemmP p, Epi epi) {
    constexpr int MI = (NB == 128 ? 4 : 2);
    const int zz = blockIdx.z;
    const int z  = (p.ksplit > 1) ? zz / p.ksplit : zz;
    const int sp = (p.ksplit > 1) ? zz % p.ksplit : 0;
    const int kcnt = p.K / p.ksplit;
    const int kbeg = sp * kcnt;
    const float* A = p.A + (size_t)z * p.aB;
    const float* B = p.B + (size_t)z * p.bB;
    const int m0 = blockIdx.y * BM, n0 = blockIdx.x * NB;

    float acc[MI][4][4];
    gemm_core<NB, BNT, CVTA, CVTB>(A, B, kbeg, kcnt, p.lda, p.ldb, m0, n0, acc);

    const int lane = threadIdx.x & 31, warp = threadIdx.x >> 5;
    const int wm = (NB == 128) ? (warp >> 2) * 64 : (warp & 3) * 32;
    const int wn = (NB == 128) ? (warp & 3) * 32 : (warp >> 2) * 32;
    const int gid = lane >> 2, tig = lane & 3;
    #pragma unroll
    for (int im = 0; im < MI; im++)
        #pragma unroll
        for (int jn = 0; jn < 4; jn++)
            #pragma unroll
            for (int qd = 0; qd < 4; qd++) {
                int r = m0 + wm + im * 16 + gid + ((qd >> 1) << 3);
                int c = n0 + wn + jn * 8 + tig * 2 + (qd & 1);
                epi(z, r, c, acc[im][jn][qd]);
            }
}

// ---------------- ATRANS GEMM kernel (step 6) ----------------
template<class Epi>
__global__ __launch_bounds__(256, 2) void gemm_at_kernel(GemmP p, Epi epi) {
    extern __shared__ float smem[];
    const int zz = blockIdx.z;
    const int z  = zz / p.ksplit;
    const int sp = zz % p.ksplit;
    const int kcnt = p.K / p.ksplit;
    const int kbeg = sp * kcnt;
    const float* A = p.A + (size_t)z * p.aB;
    const float* B = p.B + (size_t)z * p.bB;
    const int m0 = blockIdx.y * BM, n0 = blockIdx.x * 128;

    constexpr int SF = 2 * 32 * 136;
    const int tid = threadIdx.x;
    const int lane = tid & 31, warp = tid >> 5;
    const int wm = (warp >> 2) * 64, wn = (warp & 3) * 32;
    const int gid = lane >> 2, tig = lane & 3;

    float acc[4][4][4];
    #pragma unroll
    for (int i = 0; i < 4; i++)
        #pragma unroll
        for (int j = 0; j < 4; j++)
            #pragma unroll
            for (int q = 0; q < 4; q++) acc[i][j][q] = 0.f;

    const int nk = kcnt >> 5;
    load_stage_at(A, B, kbeg, p.lda, p.ldb, m0, n0, smem, smem + 32 * 136, tid);
    cpcommit();
    for (int i = 0; i < nk; i++) {
        if (i + 1 < nk) {
            float* D = smem + ((i + 1) & 1) * SF;
            load_stage_at(A, B, kbeg + ((i + 1) << 5), p.lda, p.ldb, m0, n0,
                          D, D + 32 * 136, tid);
        }
        cpcommit();
        cpwait1();
        __syncthreads();
        const float* S = smem + (i & 1) * SF;
        compute_stage_at(S, S + 32 * 136, wm, wn, gid, tig, acc);
        __syncthreads();
    }

    #pragma unroll
    for (int im = 0; im < 4; im++)
        #pragma unroll
        for (int jn = 0; jn < 4; jn++)
            #pragma unroll
            for (int qd = 0; qd < 4; qd++) {
                int r = m0 + wm + im * 16 + gid + ((qd >> 1) << 3);
                int c = n0 + wn + jn * 8 + tig * 2 + (qd & 1);
                epi(z, r, c, acc[im][jn][qd]);
            }
}

// ---------------- dual-projection kernel ----------------
struct DualP {
    const float* A;
    const float* B0; const float* B1;
    const float* bias0; const float* bias1;
    const float* mask;          // applied when z==1 (vl)
    float* out0; float* out1;
    float a0, a1;
    int K, lda, ldb, T;
};

template<int NB>
__global__ __launch_bounds__(256, 2) void dual_kernel(DualP p) {
    constexpr int MI = (NB == 128 ? 4 : 2);
    const int z = blockIdx.z;
    const float* B = z ? p.B1 : p.B0;
    const int m0 = blockIdx.y * BM, n0 = blockIdx.x * NB;

    float acc[MI][4][4];
    gemm_core<NB, false, true, true>(p.A, B, 0, p.K, p.lda, p.ldb, m0, n0, acc);

    const float* bias = z ? p.bias1 : p.bias0;
    float* out = z ? p.out1 : p.out0;
    const float alpha = z ? p.a1 : p.a0;
    const bool useMask = (p.mask != nullptr) && (z == 1);

    const int lane = threadIdx.x & 31, warp = threadIdx.x >> 5;
    const int wm = (NB == 128) ? (warp >> 2) * 64 : (warp & 3) * 32;
    const int wn = (NB == 128) ? (warp & 3) * 32 : (warp >> 2) * 32;
    const int gid = lane >> 2, tig = lane & 3;
    #pragma unroll
    for (int im = 0; im < MI; im++)
        #pragma unroll
        for (int jn = 0; jn < 4; jn++)
            #pragma unroll
            for (int qd = 0; qd < 4; qd++) {
                int r = m0 + wm + im * 16 + gid + ((qd >> 1) << 3);
                int c = n0 + wn + jn * 8 + tig * 2 + (qd & 1);
                float x = (acc[im][jn][qd] + bias[c]) * alpha;
                if (useMask) x *= p.mask[r];
                int b = r / p.T, t = r - b * p.T;
                int h = c >> 8, d = c & 255;
                out[(((size_t)(b * 8 + h)) * p.T + t) * 256 + d] = tf32r(x);
            }
}

// ---------------- attention kernel (NT core, no clamp, float2 W stores) ----------------
__global__ __launch_bounds__(256, 2) void attn_kernel(
    const float* __restrict__ q, const float* __restrict__ kmat,
    float* __restrict__ W, const float* __restrict__ maskf,
    float* __restrict__ rowZ, float* __restrict__ colZ) {
    __shared__ float s_row[128];
    __shared__ float s_col[128];
    __shared__ float s_mask[128];

    const int z = blockIdx.z;
    const float* A = q    + (size_t)z * (8192 * 256);
    const float* B = kmat + (size_t)z * (256 * 256);
    const int m0 = blockIdx.y * BM, n0 = blockIdx.x * 128;
    const int tid = threadIdx.x;

    if (tid < 128) {
        s_row[tid] = 0.f;
        s_col[tid] = 0.f;
        s_mask[tid] = maskf[(z >> 3) * 256 + n0 + tid];
    }
    // core's internal __syncthreads orders these before the epilogue

    float acc[4][4][4];
    gemm_core<128, true, false, false>(A, B, 0, 256, 256, 256, m0, n0, acc);

    const int lane = tid & 31, warp = tid >> 5;
    const int wm = (warp >> 2) * 64, wn = (warp & 3) * 32;
    const int gid = lane >> 2, tig = lane & 3;
    const size_t wbase = (size_t)z * (8192 * 256);

    float colp[4][2] = {};
    float rowp[4][2] = {};

    // Reference clips logits at +-50000 before exp; with xavier-bounded weights and
    // unit-normal inputs |logit| << 50000, so the clip is mathematically inert
    // (and softmax is shift-invariant anyway).
    #pragma unroll
    for (int im = 0; im < 4; im++)
        #pragma unroll
        for (int jn = 0; jn < 4; jn++) {
            int rl = wm + im * 16 + gid;
            int cl = wn + jn * 8 + tig * 2;
            #pragma unroll
            for (int half = 0; half < 2; half++) {      // half 0: row rl ; half 1: rl+8
                int rr = rl + half * 8;
                float w0 = __expf(acc[im][jn][half * 2 + 0]);
                float w1 = __expf(acc[im][jn][half * 2 + 1]);
                float2 wp = make_float2(tf32r(w0), tf32r(w1));
                *(float2*)&W[wbase + (size_t)(m0 + rr) * 256 + (n0 + cl)] = wp;
                colp[jn][0] += w0;
                colp[jn][1] += w1;
                rowp[im][half] += w0 * s_mask[cl] + w1 * s_mask[cl + 1];
            }
        }

    #pragma unroll
    for (int jn = 0; jn < 4; jn++)
        #pragma unroll
        for (int q1 = 0; q1 < 2; q1++) {
            float v = colp[jn][q1];
            v += __shfl_xor_sync(0xffffffffu, v, 4);
            v += __shfl_xor_sync(0xffffffffu, v, 8);
            v += __shfl_xor_sync(0xffffffffu, v, 16);
            if (gid == 0) atomicAdd(&s_col[wn + jn * 8 + tig * 2 + q1], v);
        }
    #pragma unroll
    for (int im = 0; im < 4; im++)
        #pragma unroll
        for (int qh = 0; qh < 2; qh++) {
            float v = rowp[im][qh];
            v += __shfl_xor_sync(0xffffffffu, v, 1);
            v += __shfl_xor_sync(0xffffffffu, v, 2);
            if (tig == 0) atomicAdd(&s_row[wm + im * 16 + gid + qh * 8], v);
        }

    __syncthreads();
    if (tid < 128) {
        atomicAdd(&rowZ[z * 8192 + m0 + tid], s_row[tid]);
        atomicAdd(&colZ[z * 256 + n0 + tid], s_col[tid]);
    }
}

// ---------------- small kernels ----------------
__global__ void prep_kernel(const int* __restrict__ mask,
                            float* __restrict__ outl_region,
                            const float* __restrict__ bol) {
    int i = blockIdx.x * 256 + threadIdx.x;
    int n = gridDim.x * 256;
    for (int j = i; j < 2 * 256 * 2048; j += n) g_outl1[j] = 0.f;
    // initialize out_l region with bias so split-K atomics land on top (saves a pass)
    for (int j = i; j < 512 * 768;      j += n) outl_region[j] = bol[j % 768];
    for (int j = i; j < 16 * 8192;      j += n) g_rowZ[j] = 0.f;
    for (int j = i; j < 16 * 256;       j += n) g_colZ[j] = 0.f;
    for (int j = i; j < 512;            j += n) g_maskf[j] = (float)mask[j];
}

__global__ void scale_outl1_kernel() {
    int i = blockIdx.x * 256 + threadIdx.x;   // total 2*256*2048
    int b = i / (256 * 2048);
    int rem = i - b * (256 * 2048);
    int s = rem >> 11;
    int h = (rem >> 8) & 7;
    g_outl1[i] = tf32r(g_outl1[i] / g_colZ[(b * 8 + h) * 256 + s]);
}

// ---------------- host ----------------
extern "C" void kernel_launch(void* const* d_in, const int* in_sizes, int n_in,
                              void* d_out, int out_size) {
    (void)in_sizes; (void)n_in; (void)out_size;
    const float* v    = (const float*)d_in[0];
    const float* l    = (const float*)d_in[1];
    const int*   mask = (const int*)d_in[2];
    const float* Wv   = (const float*)d_in[3];
    const float* bv   = (const float*)d_in[4];
    const float* Wl   = (const float*)d_in[5];
    const float* bl   = (const float*)d_in[6];
    const float* Wvv  = (const float*)d_in[7];
    const float* bvv  = (const float*)d_in[8];
    const float* Wvl  = (const float*)d_in[9];
    const float* bvl  = (const float*)d_in[10];
    const float* Wov  = (const float*)d_in[11];
    const float* bov  = (const float*)d_in[12];
    const float* Wol  = (const float*)d_in[13];
    const float* bol  = (const float*)d_in[14];
    float* out = (float*)d_out;

    float *pq, *pvv, *pk, *pvl, *pW, *pov1, *pol1, *prz, *pcz, *pm;
    cudaGetSymbolAddress((void**)&pq,   g_q);
    cudaGetSymbolAddress((void**)&pvv,  g_vv);
    cudaGetSymbolAddress((void**)&pk,   g_k);
    cudaGetSymbolAddress((void**)&pvl,  g_vl);
    cudaGetSymbolAddress((void**)&pW,   g_W);
    cudaGetSymbolAddress((void**)&pov1, g_outv1);
    cudaGetSymbolAddress((void**)&pol1, g_outl1);
    cudaGetSymbolAddress((void**)&prz,  g_rowZ);
    cudaGetSymbolAddress((void**)&pcz,  g_colZ);
    cudaGetSymbolAddress((void**)&pm,   g_maskf);

    constexpr int SM128_NT  = smem_new(128, true);    // 98304 (attn)
    constexpr int SM128_KN  = smem_new(128, false);   // 81920 (dual128, step4)
    constexpr int SM64_KN   = smem_new(64,  false);   // 65536 (dual64, step5, step8)

    cudaFuncSetAttribute(dual_kernel<128>, cudaFuncAttributeMaxDynamicSharedMemorySize, SM128_KN);
    cudaFuncSetAttribute(dual_kernel<64>,  cudaFuncAttributeMaxDynamicSharedMemorySize, SM64_KN);
    cudaFuncSetAttribute(attn_kernel,      cudaFuncAttributeMaxDynamicSharedMemorySize, SM128_NT);
    cudaFuncSetAttribute(gemm_kernel<128, false, false, false, EpiOutV>,
                         cudaFuncAttributeMaxDynamicSharedMemorySize, SM128_KN);
    cudaFuncSetAttribute(gemm_kernel<64, false, false, true, EpiBias>,
                         cudaFuncAttributeMaxDynamicSharedMemorySize, SM64_KN);
    cudaFuncSetAttribute(gemm_at_kernel<EpiAtomL>,
                         cudaFuncAttributeMaxDynamicSharedMemorySize, SM_AT);
    cudaFuncSetAttribute(gemm_kernel<64, false, false, true, EpiAtomPlain>,
                         cudaFuncAttributeMaxDynamicSharedMemorySize, SM64_KN);

    // 0) prep (out_l region initialized with bol; no separate bias pass)
    prep_kernel<<<1024, 256>>>(mask, out + 4194304, bol);

    // 1) q & vv projections (A=v raw, B=Wv/Wvv KN raw): M=16384 K=256 N=2048
    dual_kernel<128><<<dim3(16, 128, 2), 256, SM128_KN>>>(
        DualP{v, Wv, Wvv, bv, bvv, nullptr, pq, pvv, 0.0625f, 1.0f, 256, 256, 2048, 8192});

    // 2) k & vl projections (A=l raw): M=512 K=768 N=2048
    dual_kernel<64><<<dim3(32, 4, 2), 256, SM64_KN>>>(
        DualP{l, Wl, Wvl, bl, bvl, pm, pk, pvl, 1.0f, 1.0f, 768, 768, 2048, 256});

    // 3) W = exp(q k^T) + row/col sums. per-z: M=8192 N=256 K=256 (B=k NT)
    attn_kernel<<<dim3(2, 64, 16), 256, SM128_NT>>>(pq, pk, pW, pm, prz, pcz);

    // 4) out_v' = (W @ vl)/rowZ : A=W [t][s], B=vl [s][d] KN (pre-tf32, no cvt)
    gemm_kernel<128, false, false, false, EpiOutV><<<dim3(2, 64, 16), 256, SM128_KN>>>(
        GemmP{pW, pvl, 256, 256, 256, 8192L * 256, 256L * 256, 1},
        EpiOutV{prz, pov1});

    // 5) out_v = out_v' @ Wov + bov -> d_out : B=Wov KN raw (cvt B)
    gemm_kernel<64, false, false, true, EpiBias><<<dim3(4, 128, 1), 256, SM64_KN>>>(
        GemmP{pov1, Wov, 2048, 2048, 256, 0, 0, 1},
        EpiBias{bov, out, 256});

    // 6) out_l'_acc += W^T @ vv : ATRANS core, split-K x32 (2048 CTAs, ~99% wave eff)
    gemm_at_kernel<EpiAtomL><<<dim3(2, 2, 16 * 32), 256, SM_AT>>>(
        GemmP{pW, pvv, 8192, 256, 256, 8192L * 256, 8192L * 256, 32},
        EpiAtomL{pol1});

    // 7) out_l' /= colZ (tf32-rounded)
    scale_outl1_kernel<<<4096, 256>>>();

    // 8) out_l += out_l' @ Wol : B=Wol KN raw (cvt B), split-K x16 (768 CTAs, 86% eff)
    gemm_kernel<64, false, false, true, EpiAtomPlain><<<dim3(12, 4, 16), 256, SM64_KN>>>(
        GemmP{pol1, Wol, 2048, 2048, 768, 0, 0, 16},
        EpiAtomPlain{out + 4194304, 768});
}

// round 16
// speedup vs baseline: 1.0227x; 1.0227x over previous
#include <cuda_runtime.h>
#include <cstdint>

#define DEV_INLINE __device__ __forceinline__

// ---------------- problem constants ----------------
// B=2, TV=8192, TL=256, E=2048, H=8, D=256, VD=256, LD=768, scale=0.0625

// ---------------- scratch ----------------
__device__ __align__(16) float g_q   [(size_t)16 * 8192 * 256];   // [z][t][d] tf32
__device__ __align__(16) float g_vv  [(size_t)16 * 8192 * 256];   // [z][t][d] tf32
__device__ __align__(16) float g_k   [16 * 256 * 256];            // [z][s][d] tf32
__device__ __align__(16) float g_vl  [16 * 256 * 256];            // [z][s][d] tf32, pre-masked
__device__ __align__(16) float g_W   [(size_t)16 * 8192 * 256];   // [z][t][s] exp tf32
__device__ __align__(16) float g_outv1[(size_t)2 * 8192 * 2048];  // [b][t][E] tf32
__device__ __align__(16) float g_outl1[2 * 256 * 2048];           // [b][s][E] (split-K acc, /colZ folded)
__device__ float g_rowZ[16 * 8192];
__device__ float g_colZ[16 * 256];
__device__ float g_maskf[512];

// ---------------- helpers ----------------
DEV_INLINE float tf32r(float x) {
    uint32_t u;
    asm("cvt.rna.tf32.f32 %0, %1;" : "=r"(u) : "f"(x));
    return __uint_as_float(u);
}
DEV_INLINE uint32_t fu(float x) { return __float_as_uint(x); }
DEV_INLINE void cvt4(float4& v) {
    v.x = tf32r(v.x); v.y = tf32r(v.y); v.z = tf32r(v.z); v.w = tf32r(v.w);
}

DEV_INLINE void mma8(float (&c)[4], uint32_t a0, uint32_t a1, uint32_t a2, uint32_t a3,
                     uint32_t b0, uint32_t b1) {
    asm volatile(
        "mma.sync.aligned.m16n8k8.row.col.f32.tf32.tf32.f32 "
        "{%0,%1,%2,%3}, {%4,%5,%6,%7}, {%8,%9}, {%0,%1,%2,%3};\n"
        : "+f"(c[0]), "+f"(c[1]), "+f"(c[2]), "+f"(c[3])
        : "r"(a0), "r"(a1), "r"(a2), "r"(a3), "r"(b0), "r"(b1));
}

DEV_INLINE void cp16(float* dst, const float* src) {
    uint32_t d = (uint32_t)__cvta_generic_to_shared(dst);
    asm volatile("cp.async.cg.shared.global [%0], [%1], 16;\n" :: "r"(d), "l"(src));
}
DEV_INLINE void cpcommit() { asm volatile("cp.async.commit_group;\n"); }
DEV_INLINE void cpwait1()  { asm volatile("cp.async.wait_group 1;\n"); }

// ================= GEMM core: linear A staging + permuted-k float4 frags =================
// A row-major [M][K] staged at stride 48 -> fragment = one float4 (LDS.128).
// Logical k permutation per 16-col group g: step s uses physical k = g*16 + 4*tig + 2*s (+1).
// B NT [N][K]: same stride-48 float4 layout as A.
// B KN [K][N]: stride NB with XOR swizzle at float4 granularity:
//   element (k, col) at  k*NB + 4*((col>>2) ^ (2*((k>>2)&3))) + (col&3)
constexpr int BM = 128;
constexpr int AST = 48;
__host__ __device__ constexpr int smem_new(int NB, bool BNT) {
    int a = 128 * AST;
    int b = BNT ? NB * AST : 32 * NB;
    return 2 * (a + b) * 4;
}

template<int NB, bool BNT>
DEV_INLINE void load_stage(const float* A, const float* B, int k0,
                           int lda, int ldb, int m0, int n0,
                           float* As, float* Bs, int tid) {
    #pragma unroll
    for (int i = 0; i < 4; i++) {
        int lin = tid + i * 256;
        int r = lin >> 3, c4 = (lin & 7) << 2;
        cp16(As + r * AST + c4, A + (size_t)(m0 + r) * lda + k0 + c4);
    }
    if (BNT) {
        #pragma unroll
        for (int i = 0; i < NB / 32; i++) {
            int lin = tid + i * 256;
            int r = lin >> 3, c4 = (lin & 7) << 2;
            cp16(Bs + r * AST + c4, B + (size_t)(n0 + r) * ldb + k0 + c4);
        }
    } else {
        #pragma unroll
        for (int i = 0; i < NB / 32; i++) {
            int lin = tid + i * 256;
            int kk = lin / (NB / 4);
            int g  = lin % (NB / 4);
            int swz = g ^ (2 * ((kk >> 2) & 3));
            cp16(Bs + kk * NB + swz * 4, B + (size_t)(k0 + kk) * ldb + n0 + (g << 2));
        }
    }
}

template<int NB, bool BNT, bool CVTA, bool CVTB>
DEV_INLINE void compute_stage(const float* As, const float* Bs,
                              int wm, int wn, int gid, int tig,
                              float (&acc)[NB == 128 ? 4 : 2][4][4]) {
    constexpr int MI = (NB == 128 ? 4 : 2);
    const float4* As4 = (const float4*)As;   // row stride = 12 float4
    const float4* Bs4 = (const float4*)Bs;
    #pragma unroll
    for (int g = 0; g < 2; g++) {
        float4 Fa[MI], Fb[MI];
        #pragma unroll
        for (int im = 0; im < MI; im++) {
            int row = wm + im * 16 + gid;
            Fa[im] = As4[row * 12 + g * 4 + tig];
            Fb[im] = As4[(row + 8) * 12 + g * 4 + tig];
            if (CVTA) { cvt4(Fa[im]); cvt4(Fb[im]); }
        }
        if (BNT) {
            float4 Bf[4];
            #pragma unroll
            for (int jn = 0; jn < 4; jn++) {
                Bf[jn] = Bs4[(wn + jn * 8 + gid) * 12 + g * 4 + tig];
                if (CVTB) cvt4(Bf[jn]);
            }
            #pragma unroll
            for (int im = 0; im < MI; im++)
                #pragma unroll
                for (int jn = 0; jn < 4; jn++)
                    mma8(acc[im][jn], fu(Fa[im].x), fu(Fb[im].x), fu(Fa[im].y), fu(Fb[im].y),
                         fu(Bf[jn].x), fu(Bf[jn].y));
            #pragma unroll
            for (int im = 0; im < MI; im++)
                #pragma unroll
                for (int jn = 0; jn < 4; jn++)
                    mma8(acc[im][jn], fu(Fa[im].z), fu(Fb[im].z), fu(Fa[im].w), fu(Fb[im].w),
                         fu(Bf[jn].z), fu(Bf[jn].w));
        } else {
            #pragma unroll
            for (int s = 0; s < 2; s++) {
                const int klo = g * 16 + 4 * tig + 2 * s;
                uint32_t blo[4], bhi[4];
                #pragma unroll
                for (int jn = 0; jn < 4; jn++) {
                    int col = wn + jn * 8 + gid;
                    int scol = (((col >> 2) ^ (2 * tig)) << 2) + (col & 3);
                    float lo = Bs[klo * NB + scol];
                    float hi = Bs[(klo + 1) * NB + scol];
                    if (CVTB) { lo = tf32r(lo); hi = tf32r(hi); }
                    blo[jn] = fu(lo); bhi[jn] = fu(hi);
                }
                const int c0 = 2 * s, c1 = 2 * s + 1;
                #pragma unroll
                for (int im = 0; im < MI; im++) {
                    const float* fa = (const float*)&Fa[im];
                    const float* fb = (const float*)&Fb[im];
                    #pragma unroll
                    for (int jn = 0; jn < 4; jn++)
                        mma8(acc[im][jn], fu(fa[c0]), fu(fb[c0]), fu(fa[c1]), fu(fb[c1]),
                             blo[jn], bhi[jn]);
                }
            }
        }
    }
}

template<int NB, bool BNT, bool CVTA, bool CVTB>
DEV_INLINE void gemm_core(const float* A, const float* B, int kbeg, int kcnt,
                          int lda, int ldb, int m0, int n0,
                          float (&acc)[NB == 128 ? 4 : 2][4][4]) {
    extern __shared__ float smem[];
    constexpr int MI = (NB == 128 ? 4 : 2);
    constexpr int BSZ = BNT ? NB * AST : 32 * NB;
    constexpr int SF = 128 * AST + BSZ;

    const int tid = threadIdx.x;
    const int lane = tid & 31, warp = tid >> 5;
    const int wm = (NB == 128) ? (warp >> 2) * 64 : (warp & 3) * 32;
    const int wn = (NB == 128) ? (warp & 3) * 32 : (warp >> 2) * 32;
    const int gid = lane >> 2, tig = lane & 3;

    #pragma unroll
    for (int i = 0; i < MI; i++)
        #pragma unroll
        for (int j = 0; j < 4; j++)
            #pragma unroll
            for (int q = 0; q < 4; q++) acc[i][j][q] = 0.f;

    const int nk = kcnt >> 5;
    load_stage<NB, BNT>(A, B, kbeg, lda, ldb, m0, n0, smem, smem + 128 * AST, tid);
    cpcommit();
    for (int i = 0; i < nk; i++) {
        if (i + 1 < nk) {
            float* D = smem + ((i + 1) & 1) * SF;
            load_stage<NB, BNT>(A, B, kbeg + ((i + 1) << 5), lda, ldb, m0, n0,
                                D, D + 128 * AST, tid);
        }
        cpcommit();
        cpwait1();
        __syncthreads();
        const float* S = smem + (i & 1) * SF;
        compute_stage<NB, BNT, CVTA, CVTB>(S, S + 128 * AST, wm, wn, gid, tig, acc);
        __syncthreads();
    }
}

// ================= ATRANS core (step 6 only): A [m][k] stored at A[k*lda+m] =================
constexpr int SM_AT = 2 * (32 * 136 + 32 * 136) * 4;   // 69632

DEV_INLINE void load_stage_at(const float* A, const float* B, int k0,
                              int lda, int ldb, int m0, int n0,
                              float* As, float* Bs, int tid) {
    #pragma unroll
    for (int i = 0; i < 4; i++) {
        int lin = tid + i * 256;
        int kk = lin >> 5, m4 = (lin & 31) << 2;
        cp16(As + kk * 136 + m4, A + (size_t)(k0 + kk) * lda + m0 + m4);
    }
    #pragma unroll
    for (int i = 0; i < 4; i++) {
        int lin = tid + i * 256;
        int kk = lin >> 5, n4 = (lin & 31) << 2;
        cp16(Bs + kk * 136 + n4, B + (size_t)(k0 + kk) * ldb + n0 + n4);
    }
}

DEV_INLINE void compute_stage_at(const float* As, const float* Bs,
                                 int wm, int wn, int gid, int tig,
                                 float (&acc)[4][4][4]) {
    #pragma unroll
    for (int ks = 0; ks < 4; ks++) {
        const int kb = ks << 3;
        uint32_t a[4][4], b[4][2];
        #pragma unroll
        for (int im = 0; im < 4; im++) {
            int row = wm + im * 16 + gid;
            a[im][0] = fu(As[(kb + tig) * 136 + row]);
            a[im][1] = fu(As[(kb + tig) * 136 + row + 8]);
            a[im][2] = fu(As[(kb + tig + 4) * 136 + row]);
            a[im][3] = fu(As[(kb + tig + 4) * 136 + row + 8]);
        }
        #pragma unroll
        for (int jn = 0; jn < 4; jn++) {
            int col = wn + jn * 8 + gid;
            b[jn][0] = fu(Bs[(kb + tig) * 136 + col]);
            b[jn][1] = fu(Bs[(kb + tig + 4) * 136 + col]);
        }
        #pragma unroll
        for (int im = 0; im < 4; im++)
            #pragma unroll
            for (int jn = 0; jn < 4; jn++)
                mma8(acc[im][jn], a[im][0], a[im][1], a[im][2], a[im][3], b[jn][0], b[jn][1]);
    }
}

// ---------------- epilogues ----------------
struct EpiOutV {
    const float* rowZ; float* out;
    DEV_INLINE void operator()(int z, int r, int c, float v) const {
        int b = z >> 3, h = z & 7;
        out[((size_t)b * 8192 + r) * 2048 + h * 256 + c] = tf32r(v / rowZ[z * 8192 + r]);
    }
};
struct EpiBias {
    const float* bias; float* out; int ldc;
    DEV_INLINE void operator()(int, int r, int c, float v) const {
        out[(size_t)r * ldc + c] = v + bias[c];
    }
};
// step 6: divide each split-K partial by colZ (distributive over the sum),
// removing the separate scale pass entirely.
struct EpiAtomL {
    const float* colZ; float* out;
    DEV_INLINE void operator()(int z, int r, int c, float v) const {
        int b = z >> 3, h = z & 7;
        atomicAdd(&out[((size_t)b * 256 + r) * 2048 + h * 256 + c], v / colZ[z * 256 + r]);
    }
};
struct EpiAtomPlain {
    float* out; int ldc;
    DEV_INLINE void operator()(int, int r, int c, float v) const {
        atomicAdd(&out[(size_t)r * ldc + c], v);
    }
};

// ---------------- generic GEMM kernel ----------------
struct GemmP {
    const float* A; const float* B;
    int K, lda, ldb;
    long aB, bB;
    int ksplit;
};

template<int NB, bool BNT, bool CVTA, bool CVTB, class Epi>
__global__ __launch_bounds__(256, 2) void gemm_kernel(GemmP p, Epi epi) {
    constexpr int MI = (NB == 128 ? 4 : 2);
    const int zz = blockIdx.z;
    const int z  = (p.ksplit > 1) ? zz / p.ksplit : zz;
    const int sp = (p.ksplit > 1) ? zz % p.ksplit : 0;
    const int kcnt = p.K / p.ksplit;
    const int kbeg = sp * kcnt;
    const float* A = p.A + (size_t)z * p.aB;
    const float* B = p.B + (size_t)z * p.bB;
    const int m0 = blockIdx.y * BM, n0 = blockIdx.x * NB;

    float acc[MI][4][4];
    gemm_core<NB, BNT, CVTA, CVTB>(A, B, kbeg, kcnt, p.lda, p.ldb, m0, n0, acc);

    const int lane = threadIdx.x & 31, warp = threadIdx.x >> 5;
    const int wm = (NB == 128) ? (warp >> 2) * 64 : (warp & 3) * 32;
    const int wn = (NB == 128) ? (warp & 3) * 32 : (warp >> 2) * 32;
    const int gid = lane >> 2, tig = lane & 3;
    #pragma unroll
    for (int im = 0; im < MI; im++)
        #pragma unroll
        for (int jn = 0; jn < 4; jn++)
            #pragma unroll
            for (int qd = 0; qd < 4; qd++) {
                int r = m0 + wm + im * 16 + gid + ((qd >> 1) << 3);
                int c = n0 + wn + jn * 8 + tig * 2 + (qd & 1);
                epi(z, r, c, acc[im][jn][qd]);
            }
}

// ---------------- ATRANS GEMM kernel (step 6) ----------------
template<class Epi>
__global__ __launch_bounds__(256, 2) void gemm_at_kernel(GemmP p, Epi epi) {
    extern __shared__ float smem[];
    const int zz = blockIdx.z;
    const int z  = zz / p.ksplit;
    const int sp = zz % p.ksplit;
    const int kcnt = p.K / p.ksplit;
    const int kbeg = sp * kcnt;
    const float* A = p.A + (size_t)z * p.aB;
    const float* B = p.B + (size_t)z * p.bB;
    const int m0 = blockIdx.y * BM, n0 = blockIdx.x * 128;

    constexpr int SF = 2 * 32 * 136;
    const int tid = threadIdx.x;
    const int lane = tid & 31, warp = tid >> 5;
    const int wm = (warp >> 2) * 64, wn = (warp & 3) * 32;
    const int gid = lane >> 2, tig = lane & 3;

    float acc[4][4][4];
    #pragma unroll
    for (int i = 0; i < 4; i++)
        #pragma unroll
        for (int j = 0; j < 4; j++)
            #pragma unroll
            for (int q = 0; q < 4; q++) acc[i][j][q] = 0.f;

    const int nk = kcnt >> 5;
    load_stage_at(A, B, kbeg, p.lda, p.ldb, m0, n0, smem, smem + 32 * 136, tid);
    cpcommit();
    for (int i = 0; i < nk; i++) {
        if (i + 1 < nk) {
            float* D = smem + ((i + 1) & 1) * SF;
            load_stage_at(A, B, kbeg + ((i + 1) << 5), p.lda, p.ldb, m0, n0,
                          D, D + 32 * 136, tid);
        }
        cpcommit();
        cpwait1();
        __syncthreads();
        const float* S = smem + (i & 1) * SF;
        compute_stage_at(S, S + 32 * 136, wm, wn, gid, tig, acc);
        __syncthreads();
    }

    #pragma unroll
    for (int im = 0; im < 4; im++)
        #pragma unroll
        for (int jn = 0; jn < 4; jn++)
            #pragma unroll
            for (int qd = 0; qd < 4; qd++) {
                int r = m0 + wm + im * 16 + gid + ((qd >> 1) << 3);
                int c = n0 + wn + jn * 8 + tig * 2 + (qd & 1);
                epi(z, r, c, acc[im][jn][qd]);
            }
}

// ---------------- dual-projection kernel ----------------
struct DualP {
    const float* A;
    const float* B0; const float* B1;
    const float* bias0; const float* bias1;
    const float* mask;          // applied when z==1 (vl)
    float* out0; float* out1;
    float a0, a1;
    int K, lda, ldb, T;
};

template<int NB>
__global__ __launch_bounds__(256, 2) void dual_kernel(DualP p) {
    constexpr int MI = (NB == 128 ? 4 : 2);
    const int z = blockIdx.z;
    const float* B = z ? p.B1 : p.B0;
    const int m0 = blockIdx.y * BM, n0 = blockIdx.x * NB;

    float acc[MI][4][4];
    gemm_core<NB, false, true, true>(p.A, B, 0, p.K, p.lda, p.ldb, m0, n0, acc);

    const float* bias = z ? p.bias1 : p.bias0;
    float* out = z ? p.out1 : p.out0;
    const float alpha = z ? p.a1 : p.a0;
    const bool useMask = (p.mask != nullptr) && (z == 1);

    const int lane = threadIdx.x & 31, warp = threadIdx.x >> 5;
    const int wm = (NB == 128) ? (warp >> 2) * 64 : (warp & 3) * 32;
    const int wn = (NB == 128) ? (warp & 3) * 32 : (warp >> 2) * 32;
    const int gid = lane >> 2, tig = lane & 3;
    #pragma unroll
    for (int im = 0; im < MI; im++)
        #pragma unroll
        for (int jn = 0; jn < 4; jn++)
            #pragma unroll
            for (int qd = 0; qd < 4; qd++) {
                int r = m0 + wm + im * 16 + gid + ((qd >> 1) << 3);
                int c = n0 + wn + jn * 8 + tig * 2 + (qd & 1);
                float x = (acc[im][jn][qd] + bias[c]) * alpha;
                if (useMask) x *= p.mask[r];
                int b = r / p.T, t = r - b * p.T;
                int h = c >> 8, d = c & 255;
                out[(((size_t)(b * 8 + h)) * p.T + t) * 256 + d] = tf32r(x);
            }
}

// ---------------- attention kernel (NT core, no clamp, float2 W stores) ----------------
__global__ __launch_bounds__(256, 2) void attn_kernel(
    const float* __restrict__ q, const float* __restrict__ kmat,
    float* __restrict__ W, const float* __restrict__ maskf,
    float* __restrict__ rowZ, float* __restrict__ colZ) {
    __shared__ float s_row[128];
    __shared__ float s_col[128];
    __shared__ float s_mask[128];

    const int z = blockIdx.z;
    const float* A = q    + (size_t)z * (8192 * 256);
    const float* B = kmat + (size_t)z * (256 * 256);
    const int m0 = blockIdx.y * BM, n0 = blockIdx.x * 128;
    const int tid = threadIdx.x;

    if (tid < 128) {
        s_row[tid] = 0.f;
        s_col[tid] = 0.f;
        s_mask[tid] = maskf[(z >> 3) * 256 + n0 + tid];
    }
    // core's internal __syncthreads orders these before the epilogue

    float acc[4][4][4];
    gemm_core<128, true, false, false>(A, B, 0, 256, 256, 256, m0, n0, acc);

    const int lane = tid & 31, warp = tid >> 5;
    const int wm = (warp >> 2) * 64, wn = (warp & 3) * 32;
    const int gid = lane >> 2, tig = lane & 3;
    const size_t wbase = (size_t)z * (8192 * 256);

    float colp[4][2] = {};
    float rowp[4][2] = {};

    // Reference clips logits at +-50000 before exp; with xavier-bounded weights and
    // unit-normal inputs |logit| << 50000, so the clip is mathematically inert
    // (and softmax is shift-invariant anyway).
    #pragma unroll
    for (int im = 0; im < 4; im++)
        #pragma unroll
        for (int jn = 0; jn < 4; jn++) {
            int rl = wm + im * 16 + gid;
            int cl = wn + jn * 8 + tig * 2;
            #pragma unroll
            for (int half = 0; half < 2; half++) {      // half 0: row rl ; half 1: rl+8
                int rr = rl + half * 8;
                float w0 = __expf(acc[im][jn][half * 2 + 0]);
                float w1 = __expf(acc[im][jn][half * 2 + 1]);
                float2 wp = make_float2(tf32r(w0), tf32r(w1));
                *(float2*)&W[wbase + (size_t)(m0 + rr) * 256 + (n0 + cl)] = wp;
                colp[jn][0] += w0;
                colp[jn][1] += w1;
                rowp[im][half] += w0 * s_mask[cl] + w1 * s_mask[cl + 1];
            }
        }

    #pragma unroll
    for (int jn = 0; jn < 4; jn++)
        #pragma unroll
        for (int q1 = 0; q1 < 2; q1++) {
            float v = colp[jn][q1];
            v += __shfl_xor_sync(0xffffffffu, v, 4);
            v += __shfl_xor_sync(0xffffffffu, v, 8);
            v += __shfl_xor_sync(0xffffffffu, v, 16);
            if (gid == 0) atomicAdd(&s_col[wn + jn * 8 + tig * 2 + q1], v);
        }
    #pragma unroll
    for (int im = 0; im < 4; im++)
        #pragma unroll
        for (int qh = 0; qh < 2; qh++) {
            float v = rowp[im][qh];
            v += __shfl_xor_sync(0xffffffffu, v, 1);
            v += __shfl_xor_sync(0xffffffffu, v, 2);
            if (tig == 0) atomicAdd(&s_row[wm + im * 16 + gid + qh * 8], v);
        }

    __syncthreads();
    if (tid < 128) {
        atomicAdd(&rowZ[z * 8192 + m0 + tid], s_row[tid]);
        atomicAdd(&colZ[z * 256 + n0 + tid], s_col[tid]);
    }
}

// ---------------- small kernels ----------------
__global__ void prep_kernel(const int* __restrict__ mask,
                            float* __restrict__ outl_region,
                            const float* __restrict__ bol) {
    int i = blockIdx.x * 256 + threadIdx.x;
    int n = gridDim.x * 256;
    for (int j = i; j < 2 * 256 * 2048; j += n) g_outl1[j] = 0.f;
    // initialize out_l region with bias so split-K atomics land on top (saves a pass)
    for (int j = i; j < 512 * 768;      j += n) outl_region[j] = bol[j % 768];
    for (int j = i; j < 16 * 8192;      j += n) g_rowZ[j] = 0.f;
    for (int j = i; j < 16 * 256;       j += n) g_colZ[j] = 0.f;
    for (int j = i; j < 512;            j += n) g_maskf[j] = (float)mask[j];
}

// ---------------- host ----------------
extern "C" void kernel_launch(void* const* d_in, const int* in_sizes, int n_in,
                              void* d_out, int out_size) {
    (void)in_sizes; (void)n_in; (void)out_size;
    const float* v    = (const float*)d_in[0];
    const float* l    = (const float*)d_in[1];
    const int*   mask = (const int*)d_in[2];
    const float* Wv   = (const float*)d_in[3];
    const float* bv   = (const float*)d_in[4];
    const float* Wl   = (const float*)d_in[5];
    const float* bl   = (const float*)d_in[6];
    const float* Wvv  = (const float*)d_in[7];
    const float* bvv  = (const float*)d_in[8];
    const float* Wvl  = (const float*)d_in[9];
    const float* bvl  = (const float*)d_in[10];
    const float* Wov  = (const float*)d_in[11];
    const float* bov  = (const float*)d_in[12];
    const float* Wol  = (const float*)d_in[13];
    const float* bol  = (const float*)d_in[14];
    float* out = (float*)d_out;

    float *pq, *pvv, *pk, *pvl, *pW, *pov1, *pol1, *prz, *pcz, *pm;
    cudaGetSymbolAddress((void**)&pq,   g_q);
    cudaGetSymbolAddress((void**)&pvv,  g_vv);
    cudaGetSymbolAddress((void**)&pk,   g_k);
    cudaGetSymbolAddress((void**)&pvl,  g_vl);
    cudaGetSymbolAddress((void**)&pW,   g_W);
    cudaGetSymbolAddress((void**)&pov1, g_outv1);
    cudaGetSymbolAddress((void**)&pol1, g_outl1);
    cudaGetSymbolAddress((void**)&prz,  g_rowZ);
    cudaGetSymbolAddress((void**)&pcz,  g_colZ);
    cudaGetSymbolAddress((void**)&pm,   g_maskf);

    constexpr int SM128_NT  = smem_new(128, true);    // 98304 (attn)
    constexpr int SM128_KN  = smem_new(128, false);   // 81920 (dual128, step4)
    constexpr int SM64_KN   = smem_new(64,  false);   // 65536 (dual64, step5, step8)

    cudaFuncSetAttribute(dual_kernel<128>, cudaFuncAttributeMaxDynamicSharedMemorySize, SM128_KN);
    cudaFuncSetAttribute(dual_kernel<64>,  cudaFuncAttributeMaxDynamicSharedMemorySize, SM64_KN);
    cudaFuncSetAttribute(attn_kernel,      cudaFuncAttributeMaxDynamicSharedMemorySize, SM128_NT);
    cudaFuncSetAttribute(gemm_kernel<128, false, false, false, EpiOutV>,
                         cudaFuncAttributeMaxDynamicSharedMemorySize, SM128_KN);
    cudaFuncSetAttribute(gemm_kernel<64, false, false, true, EpiBias>,
                         cudaFuncAttributeMaxDynamicSharedMemorySize, SM64_KN);
    cudaFuncSetAttribute(gemm_at_kernel<EpiAtomL>,
                         cudaFuncAttributeMaxDynamicSharedMemorySize, SM_AT);
    cudaFuncSetAttribute(gemm_kernel<64, false, false, true, EpiAtomPlain>,
                         cudaFuncAttributeMaxDynamicSharedMemorySize, SM64_KN);

    // 0) prep (out_l region initialized with bol; no separate bias pass)
    prep_kernel<<<1024, 256>>>(mask, out + 4194304, bol);

    // 1) q & vv projections (A=v raw, B=Wv/Wvv KN raw): M=16384 K=256 N=2048
    dual_kernel<128><<<dim3(16, 128, 2), 256, SM128_KN>>>(
        DualP{v, Wv, Wvv, bv, bvv, nullptr, pq, pvv, 0.0625f, 1.0f, 256, 256, 2048, 8192});

    // 2) k & vl projections (A=l raw): M=512 K=768 N=2048
    dual_kernel<64><<<dim3(32, 4, 2), 256, SM64_KN>>>(
        DualP{l, Wl, Wvl, bl, bvl, pm, pk, pvl, 1.0f, 1.0f, 768, 768, 2048, 256});

    // 3) W = exp(q k^T) + row/col sums. per-z: M=8192 N=256 K=256 (B=k NT)
    attn_kernel<<<dim3(2, 64, 16), 256, SM128_NT>>>(pq, pk, pW, pm, prz, pcz);

    // 4) out_v' = (W @ vl)/rowZ : A=W [t][s], B=vl [s][d] KN (pre-tf32, no cvt)
    gemm_kernel<128, false, false, false, EpiOutV><<<dim3(2, 64, 16), 256, SM128_KN>>>(
        GemmP{pW, pvl, 256, 256, 256, 8192L * 256, 256L * 256, 1},
        EpiOutV{prz, pov1});

    // 5) out_v = out_v' @ Wov + bov -> d_out : B=Wov KN raw (cvt B)
    gemm_kernel<64, false, false, true, EpiBias><<<dim3(4, 128, 1), 256, SM64_KN>>>(
        GemmP{pov1, Wov, 2048, 2048, 256, 0, 0, 1},
        EpiBias{bov, out, 256});

    // 6) out_l' = (W^T @ vv)/colZ : ATRANS core, split-K x16, /colZ folded into epilogue
    gemm_at_kernel<EpiAtomL><<<dim3(2, 2, 16 * 16), 256, SM_AT>>>(
        GemmP{pW, pvv, 8192, 256, 256, 8192L * 256, 8192L * 256, 16},
        EpiAtomL{pcz, pol1});

    // 7) out_l += out_l' @ Wol : B=Wol KN raw (cvt B), split-K x8 (bias pre-seeded)
    //    (outl1 consumed as raw fp32; mma.tf32 truncates mantissa in HW — within budget)
    gemm_kernel<64, false, false, true, EpiAtomPlain><<<dim3(12, 4, 8), 256, SM64_KN>>>(
        GemmP{pol1, Wol, 2048, 2048, 768, 0, 0, 8},
        EpiAtomPlain{out + 4194304, 768});
}

// round 17
// speedup vs baseline: 1.0233x; 1.0006x over previous
#include <cuda_runtime.h>
#include <cstdint>

#define DEV_INLINE __device__ __forceinline__

// ---------------- problem constants ----------------
// B=2, TV=8192, TL=256, E=2048, H=8, D=256, VD=256, LD=768, scale=0.0625

// ---------------- scratch ----------------
__device__ __align__(16) float g_q   [(size_t)16 * 8192 * 256];   // [z][t][d] tf32
__device__ __align__(16) float g_vv  [(size_t)16 * 8192 * 256];   // [z][t][d] tf32
__device__ __align__(16) float g_k   [16 * 256 * 256];            // [z][s][d] tf32
__device__ __align__(16) float g_vl  [16 * 256 * 256];            // [z][s][d] tf32, pre-masked
__device__ __align__(16) float g_W   [(size_t)16 * 8192 * 256];   // [z][t][s] exp tf32
__device__ __align__(16) float g_outv1[(size_t)2 * 8192 * 2048];  // [b][t][E] tf32
__device__ __align__(16) float g_outl1[2 * 256 * 2048];           // [b][s][E] (split-K acc, /colZ folded)
__device__ float g_rowZ[16 * 8192];
__device__ float g_colZ[16 * 256];
__device__ float g_maskf[512];

// ---------------- helpers ----------------
DEV_INLINE float tf32r(float x) {
    uint32_t u;
    asm("cvt.rna.tf32.f32 %0, %1;" : "=r"(u) : "f"(x));
    return __uint_as_float(u);
}
DEV_INLINE uint32_t fu(float x) { return __float_as_uint(x); }
DEV_INLINE void cvt4(float4& v) {
    v.x = tf32r(v.x); v.y = tf32r(v.y); v.z = tf32r(v.z); v.w = tf32r(v.w);
}

DEV_INLINE void mma8(float (&c)[4], uint32_t a0, uint32_t a1, uint32_t a2, uint32_t a3,
                     uint32_t b0, uint32_t b1) {
    asm volatile(
        "mma.sync.aligned.m16n8k8.row.col.f32.tf32.tf32.f32 "
        "{%0,%1,%2,%3}, {%4,%5,%6,%7}, {%8,%9}, {%0,%1,%2,%3};\n"
        : "+f"(c[0]), "+f"(c[1]), "+f"(c[2]), "+f"(c[3])
        : "r"(a0), "r"(a1), "r"(a2), "r"(a3), "r"(b0), "r"(b1));
}

DEV_INLINE void cp16(float* dst, const float* src) {
    uint32_t d = (uint32_t)__cvta_generic_to_shared(dst);
    asm volatile("cp.async.cg.shared.global [%0], [%1], 16;\n" :: "r"(d), "l"(src));
}
DEV_INLINE void cpcommit() { asm volatile("cp.async.commit_group;\n"); }
DEV_INLINE void cpwait1()  { asm volatile("cp.async.wait_group 1;\n"); }

// ================= GEMM core: linear A staging + permuted-k float4 frags =================
constexpr int BM = 128;
constexpr int AST = 48;
__host__ __device__ constexpr int smem_new(int NB, bool BNT) {
    int a = 128 * AST;
    int b = BNT ? NB * AST : 32 * NB;
    return 2 * (a + b) * 4;
}

template<int NB, bool BNT>
DEV_INLINE void load_stage(const float* A, const float* B, int k0,
                           int lda, int ldb, int m0, int n0,
                           float* As, float* Bs, int tid) {
    #pragma unroll
    for (int i = 0; i < 4; i++) {
        int lin = tid + i * 256;
        int r = lin >> 3, c4 = (lin & 7) << 2;
        cp16(As + r * AST + c4, A + (size_t)(m0 + r) * lda + k0 + c4);
    }
    if (BNT) {
        #pragma unroll
        for (int i = 0; i < NB / 32; i++) {
            int lin = tid + i * 256;
            int r = lin >> 3, c4 = (lin & 7) << 2;
            cp16(Bs + r * AST + c4, B + (size_t)(n0 + r) * ldb + k0 + c4);
        }
    } else {
        #pragma unroll
        for (int i = 0; i < NB / 32; i++) {
            int lin = tid + i * 256;
            int kk = lin / (NB / 4);
            int g  = lin % (NB / 4);
            int swz = g ^ (2 * ((kk >> 2) & 3));
            cp16(Bs + kk * NB + swz * 4, B + (size_t)(k0 + kk) * ldb + n0 + (g << 2));
        }
    }
}

template<int NB, bool BNT, bool CVTA, bool CVTB>
DEV_INLINE void compute_stage(const float* As, const float* Bs,
                              int wm, int wn, int gid, int tig,
                              float (&acc)[NB == 128 ? 4 : 2][4][4]) {
    constexpr int MI = (NB == 128 ? 4 : 2);
    const float4* As4 = (const float4*)As;   // row stride = 12 float4
    const float4* Bs4 = (const float4*)Bs;
    #pragma unroll
    for (int g = 0; g < 2; g++) {
        float4 Fa[MI], Fb[MI];
        #pragma unroll
        for (int im = 0; im < MI; im++) {
            int row = wm + im * 16 + gid;
            Fa[im] = As4[row * 12 + g * 4 + tig];
            Fb[im] = As4[(row + 8) * 12 + g * 4 + tig];
            if (CVTA) { cvt4(Fa[im]); cvt4(Fb[im]); }
        }
        if (BNT) {
            float4 Bf[4];
            #pragma unroll
            for (int jn = 0; jn < 4; jn++) {
                Bf[jn] = Bs4[(wn + jn * 8 + gid) * 12 + g * 4 + tig];
                if (CVTB) cvt4(Bf[jn]);
            }
            #pragma unroll
            for (int im = 0; im < MI; im++)
                #pragma unroll
                for (int jn = 0; jn < 4; jn++)
                    mma8(acc[im][jn], fu(Fa[im].x), fu(Fb[im].x), fu(Fa[im].y), fu(Fb[im].y),
                         fu(Bf[jn].x), fu(Bf[jn].y));
            #pragma unroll
            for (int im = 0; im < MI; im++)
                #pragma unroll
                for (int jn = 0; jn < 4; jn++)
                    mma8(acc[im][jn], fu(Fa[im].z), fu(Fb[im].z), fu(Fa[im].w), fu(Fb[im].w),
                         fu(Bf[jn].z), fu(Bf[jn].w));
        } else {
            #pragma unroll
            for (int s = 0; s < 2; s++) {
                const int klo = g * 16 + 4 * tig + 2 * s;
                uint32_t blo[4], bhi[4];
                #pragma unroll
                for (int jn = 0; jn < 4; jn++) {
                    int col = wn + jn * 8 + gid;
                    int scol = (((col >> 2) ^ (2 * tig)) << 2) + (col & 3);
                    float lo = Bs[klo * NB + scol];
                    float hi = Bs[(klo + 1) * NB + scol];
                    if (CVTB) { lo = tf32r(lo); hi = tf32r(hi); }
                    blo[jn] = fu(lo); bhi[jn] = fu(hi);
                }
                const int c0 = 2 * s, c1 = 2 * s + 1;
                #pragma unroll
                for (int im = 0; im < MI; im++) {
                    const float* fa = (const float*)&Fa[im];
                    const float* fb = (const float*)&Fb[im];
                    #pragma unroll
                    for (int jn = 0; jn < 4; jn++)
                        mma8(acc[im][jn], fu(fa[c0]), fu(fb[c0]), fu(fa[c1]), fu(fb[c1]),
                             blo[jn], bhi[jn]);
                }
            }
        }
    }
}

template<int NB, bool BNT, bool CVTA, bool CVTB>
DEV_INLINE void gemm_core(const float* A, const float* B, int kbeg, int kcnt,
                          int lda, int ldb, int m0, int n0,
                          float (&acc)[NB == 128 ? 4 : 2][4][4]) {
    extern __shared__ float smem[];
    constexpr int MI = (NB == 128 ? 4 : 2);
    constexpr int BSZ = BNT ? NB * AST : 32 * NB;
    constexpr int SF = 128 * AST + BSZ;

    const int tid = threadIdx.x;
    const int lane = tid & 31, warp = tid >> 5;
    const int wm = (NB == 128) ? (warp >> 2) * 64 : (warp & 3) * 32;
    const int wn = (NB == 128) ? (warp & 3) * 32 : (warp >> 2) * 32;
    const int gid = lane >> 2, tig = lane & 3;

    #pragma unroll
    for (int i = 0; i < MI; i++)
        #pragma unroll
        for (int j = 0; j < 4; j++)
            #pragma unroll
            for (int q = 0; q < 4; q++) acc[i][j][q] = 0.f;

    const int nk = kcnt >> 5;
    load_stage<NB, BNT>(A, B, kbeg, lda, ldb, m0, n0, smem, smem + 128 * AST, tid);
    cpcommit();
    for (int i = 0; i < nk; i++) {
        if (i + 1 < nk) {
            float* D = smem + ((i + 1) & 1) * SF;
            load_stage<NB, BNT>(A, B, kbeg + ((i + 1) << 5), lda, ldb, m0, n0,
                                D, D + 128 * AST, tid);
        }
        cpcommit();
        cpwait1();
        __syncthreads();
        const float* S = smem + (i & 1) * SF;
        compute_stage<NB, BNT, CVTA, CVTB>(S, S + 128 * AST, wm, wn, gid, tig, acc);
        __syncthreads();
    }
}

// ================= ATRANS core (step 6): A [m][k] stored at A[k*lda+m] =================
constexpr int SM_AT = 2 * (32 * 136 + 32 * 136) * 4;   // 69632

DEV_INLINE void load_stage_at(const float* A, const float* B, int k0,
                              int lda, int ldb, int m0, int n0,
                              float* As, float* Bs, int tid) {
    #pragma unroll
    for (int i = 0; i < 4; i++) {
        int lin = tid + i * 256;
        int kk = lin >> 5, m4 = (lin & 31) << 2;
        cp16(As + kk * 136 + m4, A + (size_t)(k0 + kk) * lda + m0 + m4);
    }
    #pragma unroll
    for (int i = 0; i < 4; i++) {
        int lin = tid + i * 256;
        int kk = lin >> 5, n4 = (lin & 31) << 2;
        cp16(Bs + kk * 136 + n4, B + (size_t)(k0 + kk) * ldb + n0 + n4);
    }
}

DEV_INLINE void compute_stage_at(const float* As, const float* Bs,
                                 int wm, int wn, int gid, int tig,
                                 float (&acc)[4][4][4]) {
    #pragma unroll
    for (int ks = 0; ks < 4; ks++) {
        const int kb = ks << 3;
        uint32_t a[4][4], b[4][2];
        #pragma unroll
        for (int im = 0; im < 4; im++) {
            int row = wm + im * 16 + gid;
            a[im][0] = fu(As[(kb + tig) * 136 + row]);
            a[im][1] = fu(As[(kb + tig) * 136 + row + 8]);
            a[im][2] = fu(As[(kb + tig + 4) * 136 + row]);
            a[im][3] = fu(As[(kb + tig + 4) * 136 + row + 8]);
        }
        #pragma unroll
        for (int jn = 0; jn < 4; jn++) {
            int col = wn + jn * 8 + gid;
            b[jn][0] = fu(Bs[(kb + tig) * 136 + col]);
            b[jn][1] = fu(Bs[(kb + tig + 4) * 136 + col]);
        }
        #pragma unroll
        for (int im = 0; im < 4; im++)
            #pragma unroll
            for (int jn = 0; jn < 4; jn++)
                mma8(acc[im][jn], a[im][0], a[im][1], a[im][2], a[im][3], b[jn][0], b[jn][1]);
    }
}

// ---------------- epilogues ----------------
struct EpiOutV {
    const float* rowZ; float* out;
    DEV_INLINE void operator()(int z, int r, int c, float v) const {
        int b = z >> 3, h = z & 7;
        out[((size_t)b * 8192 + r) * 2048 + h * 256 + c] = tf32r(v / rowZ[z * 8192 + r]);
    }
};
struct EpiBias {
    const float* bias; float* out; int ldc;
    DEV_INLINE void operator()(int, int r, int c, float v) const {
        out[(size_t)r * ldc + c] = v + bias[c];
    }
};
// step 6: divide each split-K partial by colZ (distributive over the sum).
struct EpiAtomL {
    const float* colZ; float* out;
    DEV_INLINE void operator()(int z, int r, int c, float v) const {
        int b = z >> 3, h = z & 7;
        atomicAdd(&out[((size_t)b * 256 + r) * 2048 + h * 256 + c], v / colZ[z * 256 + r]);
    }
};
struct EpiAtomPlain {
    float* out; int ldc;
    DEV_INLINE void operator()(int, int r, int c, float v) const {
        atomicAdd(&out[(size_t)r * ldc + c], v);
    }
};

// ---------------- generic GEMM bodies ----------------
struct GemmP {
    const float* A; const float* B;
    int K, lda, ldb;
    long aB, bB;
    int ksplit;
};

template<int NB, bool BNT, bool CVTA, bool CVTB, class Epi>
DEV_INLINE void gemm_body(const GemmP& p, const Epi& epi, int zz, int m0, int n0) {
    constexpr int MI = (NB == 128 ? 4 : 2);
    const int z  = (p.ksplit > 1) ? zz / p.ksplit : zz;
    const int sp = (p.ksplit > 1) ? zz % p.ksplit : 0;
    const int kcnt = p.K / p.ksplit;
    const int kbeg = sp * kcnt;
    const float* A = p.A + (size_t)z * p.aB;
    const float* B = p.B + (size_t)z * p.bB;

    float acc[MI][4][4];
    gemm_core<NB, BNT, CVTA, CVTB>(A, B, kbeg, kcnt, p.lda, p.ldb, m0, n0, acc);

    const int lane = threadIdx.x & 31, warp = threadIdx.x >> 5;
    const int wm = (NB == 128) ? (warp >> 2) * 64 : (warp & 3) * 32;
    const int wn = (NB == 128) ? (warp & 3) * 32 : (warp >> 2) * 32;
    const int gid = lane >> 2, tig = lane & 3;
    #pragma unroll
    for (int im = 0; im < MI; im++)
        #pragma unroll
        for (int jn = 0; jn < 4; jn++)
            #pragma unroll
            for (int qd = 0; qd < 4; qd++) {
                int r = m0 + wm + im * 16 + gid + ((qd >> 1) << 3);
                int c = n0 + wn + jn * 8 + tig * 2 + (qd & 1);
                epi(z, r, c, acc[im][jn][qd]);
            }
}

template<int NB, bool BNT, bool CVTA, bool CVTB, class Epi>
__global__ __launch_bounds__(256, 2) void gemm_kernel(GemmP p, Epi epi) {
    gemm_body<NB, BNT, CVTA, CVTB>(p, epi, blockIdx.z, blockIdx.y * BM, blockIdx.x * NB);
}

// ---------------- ATRANS body (step 6) ----------------
template<class Epi>
DEV_INLINE void at_body(const GemmP& p, const Epi& epi, int zz, int m0, int n0) {
    extern __shared__ float smem[];
    const int z  = zz / p.ksplit;
    const int sp = zz % p.ksplit;
    const int kcnt = p.K / p.ksplit;
    const int kbeg = sp * kcnt;
    const float* A = p.A + (size_t)z * p.aB;
    const float* B = p.B + (size_t)z * p.bB;

    constexpr int SF = 2 * 32 * 136;
    const int tid = threadIdx.x;
    const int lane = tid & 31, warp = tid >> 5;
    const int wm = (warp >> 2) * 64, wn = (warp & 3) * 32;
    const int gid = lane >> 2, tig = lane & 3;

    float acc[4][4][4];
    #pragma unroll
    for (int i = 0; i < 4; i++)
        #pragma unroll
        for (int j = 0; j < 4; j++)
            #pragma unroll
            for (int q = 0; q < 4; q++) acc[i][j][q] = 0.f;

    const int nk = kcnt >> 5;
    load_stage_at(A, B, kbeg, p.lda, p.ldb, m0, n0, smem, smem + 32 * 136, tid);
    cpcommit();
    for (int i = 0; i < nk; i++) {
        if (i + 1 < nk) {
            float* D = smem + ((i + 1) & 1) * SF;
            load_stage_at(A, B, kbeg + ((i + 1) << 5), p.lda, p.ldb, m0, n0,
                          D, D + 32 * 136, tid);
        }
        cpcommit();
        cpwait1();
        __syncthreads();
        const float* S = smem + (i & 1) * SF;
        compute_stage_at(S, S + 32 * 136, wm, wn, gid, tig, acc);
        __syncthreads();
    }

    #pragma unroll
    for (int im = 0; im < 4; im++)
        #pragma unroll
        for (int jn = 0; jn < 4; jn++)
            #pragma unroll
            for (int qd = 0; qd < 4; qd++) {
                int r = m0 + wm + im * 16 + gid + ((qd >> 1) << 3);
                int c = n0 + wn + jn * 8 + tig * 2 + (qd & 1);
                epi(z, r, c, acc[im][jn][qd]);
            }
}

// ---------------- dual-projection body ----------------
struct DualP {
    const float* A;
    const float* B0; const float* B1;
    const float* bias0; const float* bias1;
    const float* mask;          // applied when z==1 (vl)
    float* out0; float* out1;
    float a0, a1;
    int K, lda, ldb, T;
};

template<int NB>
DEV_INLINE void dual_body(const DualP& p, int z, int m0, int n0) {
    constexpr int MI = (NB == 128 ? 4 : 2);
    const float* B = z ? p.B1 : p.B0;

    float acc[MI][4][4];
    gemm_core<NB, false, true, true>(p.A, B, 0, p.K, p.lda, p.ldb, m0, n0, acc);

    const float* bias = z ? p.bias1 : p.bias0;
    float* out = z ? p.out1 : p.out0;
    const float alpha = z ? p.a1 : p.a0;
    const bool useMask = (p.mask != nullptr) && (z == 1);

    const int lane = threadIdx.x & 31, warp = threadIdx.x >> 5;
    const int wm = (NB == 128) ? (warp >> 2) * 64 : (warp & 3) * 32;
    const int wn = (NB == 128) ? (warp & 3) * 32 : (warp >> 2) * 32;
    const int gid = lane >> 2, tig = lane & 3;
    #pragma unroll
    for (int im = 0; im < MI; im++)
        #pragma unroll
        for (int jn = 0; jn < 4; jn++)
            #pragma unroll
            for (int qd = 0; qd < 4; qd++) {
                int r = m0 + wm + im * 16 + gid + ((qd >> 1) << 3);
                int c = n0 + wn + jn * 8 + tig * 2 + (qd & 1);
                float x = (acc[im][jn][qd] + bias[c]) * alpha;
                if (useMask) x *= p.mask[r];
                int b = r / p.T, t = r - b * p.T;
                int h = c >> 8, d = c & 255;
                out[(((size_t)(b * 8 + h)) * p.T + t) * 256 + d] = tf32r(x);
            }
}

// ---------------- merged kernels (tail-filling) ----------------
// steps 1+2: ids [0,4096) -> dual128 (16,128,2); ids [4096,4352) -> dual64 (32,4,2)
__global__ __launch_bounds__(256, 2) void dual12_kernel(DualP p1, DualP p2) {
    int id = blockIdx.x;
    if (id < 4096) {
        int z = id >> 11;
        int rem = id & 2047;
        dual_body<128>(p1, z, (rem >> 4) * 128, (rem & 15) * 128);
    } else {
        int id2 = id - 4096;
        int z = id2 >> 7;
        int rem = id2 & 127;
        dual_body<64>(p2, z, (rem >> 5) * 128, (rem & 31) * 64);
    }
}

// steps 6+5: ids [0,1024) -> step6 ATRANS (2,2,256); ids [1024,1536) -> step5 (4,128)
__global__ __launch_bounds__(256, 2) void step56_kernel(GemmP p6, EpiAtomL e6,
                                                        GemmP p5, EpiBias e5) {
    int id = blockIdx.x;
    if (id < 1024) {
        at_body(p6, e6, id >> 2, ((id >> 1) & 1) * 128, (id & 1) * 128);
    } else {
        int id2 = id - 1024;
        gemm_body<64, false, false, true>(p5, e5, 0, (id2 >> 2) * 128, (id2 & 3) * 64);
    }
}

// ---------------- attention kernel (NT core, no clamp, float2 W stores) ----------------
__global__ __launch_bounds__(256, 2) void attn_kernel(
    const float* __restrict__ q, const float* __restrict__ kmat,
    float* __restrict__ W, const float* __restrict__ maskf,
    float* __restrict__ rowZ, float* __restrict__ colZ) {
    __shared__ float s_row[128];
    __shared__ float s_col[128];
    __shared__ float s_mask[128];

    const int z = blockIdx.z;
    const float* A = q    + (size_t)z * (8192 * 256);
    const float* B = kmat + (size_t)z * (256 * 256);
    const int m0 = blockIdx.y * BM, n0 = blockIdx.x * 128;
    const int tid = threadIdx.x;

    if (tid < 128) {
        s_row[tid] = 0.f;
        s_col[tid] = 0.f;
        s_mask[tid] = maskf[(z >> 3) * 256 + n0 + tid];
    }
    // core's internal __syncthreads orders these before the epilogue

    float acc[4][4][4];
    gemm_core<128, true, false, false>(A, B, 0, 256, 256, 256, m0, n0, acc);

    const int lane = tid & 31, warp = tid >> 5;
    const int wm = (warp >> 2) * 64, wn = (warp & 3) * 32;
    const int gid = lane >> 2, tig = lane & 3;
    const size_t wbase = (size_t)z * (8192 * 256);

    float colp[4][2] = {};
    float rowp[4][2] = {};

    // Reference clips logits at +-50000 before exp; |logit| << 50000 here, and
    // softmax is shift-invariant — clip omitted (mathematically inert).
    #pragma unroll
    for (int im = 0; im < 4; im++)
        #pragma unroll
        for (int jn = 0; jn < 4; jn++) {
            int rl = wm + im * 16 + gid;
            int cl = wn + jn * 8 + tig * 2;
            #pragma unroll
            for (int half = 0; half < 2; half++) {
                int rr = rl + half * 8;
                float w0 = __expf(acc[im][jn][half * 2 + 0]);
                float w1 = __expf(acc[im][jn][half * 2 + 1]);
                float2 wp = make_float2(tf32r(w0), tf32r(w1));
                *(float2*)&W[wbase + (size_t)(m0 + rr) * 256 + (n0 + cl)] = wp;
                colp[jn][0] += w0;
                colp[jn][1] += w1;
                rowp[im][half] += w0 * s_mask[cl] + w1 * s_mask[cl + 1];
            }
        }

    #pragma unroll
    for (int jn = 0; jn < 4; jn++)
        #pragma unroll
        for (int q1 = 0; q1 < 2; q1++) {
            float v = colp[jn][q1];
            v += __shfl_xor_sync(0xffffffffu, v, 4);
            v += __shfl_xor_sync(0xffffffffu, v, 8);
            v += __shfl_xor_sync(0xffffffffu, v, 16);
            if (gid == 0) atomicAdd(&s_col[wn + jn * 8 + tig * 2 + q1], v);
        }
    #pragma unroll
    for (int im = 0; im < 4; im++)
        #pragma unroll
        for (int qh = 0; qh < 2; qh++) {
            float v = rowp[im][qh];
            v += __shfl_xor_sync(0xffffffffu, v, 1);
            v += __shfl_xor_sync(0xffffffffu, v, 2);
            if (tig == 0) atomicAdd(&s_row[wm + im * 16 + gid + qh * 8], v);
        }

    __syncthreads();
    if (tid < 128) {
        atomicAdd(&rowZ[z * 8192 + m0 + tid], s_row[tid]);
        atomicAdd(&colZ[z * 256 + n0 + tid], s_col[tid]);
    }
}

// ---------------- small kernels ----------------
__global__ void prep_kernel(const int* __restrict__ mask,
                            float* __restrict__ outl_region,
                            const float* __restrict__ bol) {
    int i = blockIdx.x * 256 + threadIdx.x;
    int n = gridDim.x * 256;
    for (int j = i; j < 2 * 256 * 2048; j += n) g_outl1[j] = 0.f;
    for (int j = i; j < 512 * 768;      j += n) outl_region[j] = bol[j % 768];
    for (int j = i; j < 16 * 8192;      j += n) g_rowZ[j] = 0.f;
    for (int j = i; j < 16 * 256;       j += n) g_colZ[j] = 0.f;
    for (int j = i; j < 512;            j += n) g_maskf[j] = (float)mask[j];
}

// ---------------- host ----------------
extern "C" void kernel_launch(void* const* d_in, const int* in_sizes, int n_in,
                              void* d_out, int out_size) {
    (void)in_sizes; (void)n_in; (void)out_size;
    const float* v    = (const float*)d_in[0];
    const float* l    = (const float*)d_in[1];
    const int*   mask = (const int*)d_in[2];
    const float* Wv   = (const float*)d_in[3];
    const float* bv   = (const float*)d_in[4];
    const float* Wl   = (const float*)d_in[5];
    const float* bl   = (const float*)d_in[6];
    const float* Wvv  = (const float*)d_in[7];
    const float* bvv  = (const float*)d_in[8];
    const float* Wvl  = (const float*)d_in[9];
    const float* bvl  = (const float*)d_in[10];
    const float* Wov  = (const float*)d_in[11];
    const float* bov  = (const float*)d_in[12];
    const float* Wol  = (const float*)d_in[13];
    const float* bol  = (const float*)d_in[14];
    float* out = (float*)d_out;

    float *pq, *pvv, *pk, *pvl, *pW, *pov1, *pol1, *prz, *pcz, *pm;
    cudaGetSymbolAddress((void**)&pq,   g_q);
    cudaGetSymbolAddress((void**)&pvv,  g_vv);
    cudaGetSymbolAddress((void**)&pk,   g_k);
    cudaGetSymbolAddress((void**)&pvl,  g_vl);
    cudaGetSymbolAddress((void**)&pW,   g_W);
    cudaGetSymbolAddress((void**)&pov1, g_outv1);
    cudaGetSymbolAddress((void**)&pol1, g_outl1);
    cudaGetSymbolAddress((void**)&prz,  g_rowZ);
    cudaGetSymbolAddress((void**)&pcz,  g_colZ);
    cudaGetSymbolAddress((void**)&pm,   g_maskf);

    constexpr int SM128_NT = smem_new(128, true);    // 98304 (attn)
    constexpr int SM128_KN = smem_new(128, false);   // 81920 (dual128, step4)
    constexpr int SM64_KN  = smem_new(64,  false);   // 65536 (step5)
    constexpr int SM_D12   = SM128_KN;               // max(81920, 65536)
    constexpr int SM_S56   = SM_AT;                  // max(69632, 65536)

    cudaFuncSetAttribute(dual12_kernel, cudaFuncAttributeMaxDynamicSharedMemorySize, SM_D12);
    cudaFuncSetAttribute(step56_kernel, cudaFuncAttributeMaxDynamicSharedMemorySize, SM_S56);
    cudaFuncSetAttribute(attn_kernel,   cudaFuncAttributeMaxDynamicSharedMemorySize, SM128_NT);
    cudaFuncSetAttribute(gemm_kernel<128, false, false, false, EpiOutV>,
                         cudaFuncAttributeMaxDynamicSharedMemorySize, SM128_KN);
    cudaFuncSetAttribute(gemm_kernel<64, false, false, true, EpiAtomPlain>,
                         cudaFuncAttributeMaxDynamicSharedMemorySize, SM64_KN);

    // 0) prep (out_l region initialized with bol)
    prep_kernel<<<1024, 256>>>(mask, out + 4194304, bol);

    // 1+2) q/vv (4096 blocks) + k/vl (256 blocks) merged: dual64 fills dual128's tail
    dual12_kernel<<<4352, 256, SM_D12>>>(
        DualP{v, Wv, Wvv, bv, bvv, nullptr, pq, pvv, 0.0625f, 1.0f, 256, 256, 2048, 8192},
        DualP{l, Wl, Wvl, bl, bvl, pm, pk, pvl, 1.0f, 1.0f, 768, 768, 2048, 256});

    // 3) W = exp(q k^T) + row/col sums. per-z: M=8192 N=256 K=256 (B=k NT)
    attn_kernel<<<dim3(2, 64, 16), 256, SM128_NT>>>(pq, pk, pW, pm, prz, pcz);

    // 4) out_v' = (W @ vl)/rowZ : A=W [t][s], B=vl [s][d] KN (pre-tf32, no cvt)
    gemm_kernel<128, false, false, false, EpiOutV><<<dim3(2, 64, 16), 256, SM128_KN>>>(
        GemmP{pW, pvl, 256, 256, 256, 8192L * 256, 256L * 256, 1},
        EpiOutV{prz, pov1});

    // 5+6) merged: step6 = (W^T@vv)/colZ split-K x16 (1024 blocks) +
    //              step5 = out_v'@Wov + bov -> d_out (512 blocks, fills step6's tail)
    step56_kernel<<<1536, 256, SM_S56>>>(
        GemmP{pW, pvv, 8192, 256, 256, 8192L * 256, 8192L * 256, 16},
        EpiAtomL{pcz, pol1},
        GemmP{pov1, Wov, 2048, 2048, 256, 0, 0, 1},
        EpiBias{bov, out, 256});

    // 7) out_l += out_l' @ Wol : B=Wol KN raw (cvt B), split-K x8 (bias pre-seeded;
    //    outl1 consumed as raw fp32 — HW tf32 truncation, within error budget)
    gemm_kernel<64, false, false, true, EpiAtomPlain><<<dim3(12, 4, 8), 256, SM64_KN>>>(
        GemmP{pol1, Wol, 2048, 2048, 768, 0, 0, 8},
        EpiAtomPlain{out + 4194304, 768});
}